// round 13
// baseline (speedup 1.0000x reference)
#include <cuda_runtime.h>
#include <math.h>

#define Hh 512
#define Bb 32
#define Ss 48
#define Tt 48
#define G3 1536

// ---- scratch layout (floats) ----
#define OFF_X      0
#define OFF_GIF    786432
#define OFF_GIB    3145728
#define OFF_GID    5505024
#define OFF_HS     7864320
#define OFF_A2     8650752
#define OFF_C1     10223616
#define OFF_ENCOUT 11010048
#define OFF_HENCF  11796480
#define OFF_HENCB  11829248
#define OFF_HD     11862016
#define SCR_TOTAL  11894784

static __device__ float g_scratch[SCR_TOTAL];

// ---- packed f32x2 helpers (FFMA2) ----
__device__ __forceinline__ unsigned long long dup2(float x) {
    unsigned long long r;
    asm("mov.b64 %0, {%1, %1};" : "=l"(r) : "f"(x));
    return r;
}
__device__ __forceinline__ void ffma2(unsigned long long &c, unsigned long long a,
                                      unsigned long long b) {
    asm("fma.rn.f32x2 %0, %1, %2, %0;" : "+l"(c) : "l"(a), "l"(b));
}
__device__ __forceinline__ float2 unpk(unsigned long long v) {
    float2 r;
    asm("mov.b64 {%0, %1}, %2;" : "=f"(r.x), "=f"(r.y) : "l"(v));
    return r;
}

// ---- C[M,N] = A[M,K] @ W[N,K]^T + bias, optional tanh. 128x128x16 tiles ----
__global__ void __launch_bounds__(256) gemm_wt(
    const float* __restrict__ A, const float* __restrict__ W,
    const float* __restrict__ bias, float* __restrict__ C,
    int M, int N, int K, int act)
{
    __shared__ float As[16][132];
    __shared__ float Bs[16][132];
    const int m0 = blockIdx.x * 128;
    const int n0 = blockIdx.y * 128;
    const int tid = threadIdx.x;
    const int tx = tid & 15, ty = tid >> 4;
    const int lrow = tid >> 2;
    const int lk = (tid & 3) << 2;

    unsigned long long acc[8][4];
#pragma unroll
    for (int i = 0; i < 8; i++)
#pragma unroll
        for (int j = 0; j < 4; j++) acc[i][j] = 0ULL;

    for (int k0 = 0; k0 < K; k0 += 16) {
#pragma unroll
        for (int r = 0; r < 2; r++) {
            int row = lrow + r * 64;
            float4 va = *(const float4*)&A[(size_t)(m0 + row) * K + k0 + lk];
            As[lk + 0][row] = va.x; As[lk + 1][row] = va.y;
            As[lk + 2][row] = va.z; As[lk + 3][row] = va.w;
            float4 vw = *(const float4*)&W[(size_t)(n0 + row) * K + k0 + lk];
            Bs[lk + 0][row] = vw.x; Bs[lk + 1][row] = vw.y;
            Bs[lk + 2][row] = vw.z; Bs[lk + 3][row] = vw.w;
        }
        __syncthreads();
#pragma unroll
        for (int k = 0; k < 16; k++) {
            float4 a0 = *(const float4*)&As[k][ty * 8];
            float4 a1 = *(const float4*)&As[k][ty * 8 + 4];
            unsigned long long b0 = *(const unsigned long long*)&Bs[k][tx * 8];
            unsigned long long b1 = *(const unsigned long long*)&Bs[k][tx * 8 + 2];
            unsigned long long b2 = *(const unsigned long long*)&Bs[k][tx * 8 + 4];
            unsigned long long b3 = *(const unsigned long long*)&Bs[k][tx * 8 + 6];
            float av[8] = {a0.x, a0.y, a0.z, a0.w, a1.x, a1.y, a1.z, a1.w};
#pragma unroll
            for (int i = 0; i < 8; i++) {
                unsigned long long a2 = dup2(av[i]);
                ffma2(acc[i][0], a2, b0);
                ffma2(acc[i][1], a2, b1);
                ffma2(acc[i][2], a2, b2);
                ffma2(acc[i][3], a2, b3);
            }
        }
        __syncthreads();
    }
#pragma unroll
    for (int i = 0; i < 8; i++) {
        int m = m0 + ty * 8 + i;
#pragma unroll
        for (int j = 0; j < 4; j++) {
            int n = n0 + tx * 8 + j * 2;
            float2 v = unpk(acc[i][j]);
            v.x += bias[n]; v.y += bias[n + 1];
            if (act) { v.x = tanhf(v.x); v.y = tanhf(v.y); }
            *(float2*)&C[(size_t)m * N + n] = v;
        }
    }
}

// ---- embedding gathers ----
__global__ void embed_enc(const int* __restrict__ toks, const float* __restrict__ emb,
                          float* __restrict__ X)
{
    int row = blockIdx.x;
    int tok = toks[row];
    const float4* s = (const float4*)(emb + (size_t)tok * Hh);
    float4* d = (float4*)(X + (size_t)row * Hh);
    d[threadIdx.x] = s[threadIdx.x];
}
__global__ void embed_dec(const int* __restrict__ tgt, const float* __restrict__ emb,
                          float* __restrict__ X)
{
    int row = blockIdx.x;
    int tok = (row < Bb) ? 1 : tgt[row - Bb];   // SOS=1, then target[t-1]
    const float4* s = (const float4*)(emb + (size_t)tok * Hh);
    float4* d = (float4*)(X + (size_t)row * Hh);
    d[threadIdx.x] = s[threadIdx.x];
}

__global__ void zero_kernel(float* __restrict__ p, int n4)
{
    int i = blockIdx.x * blockDim.x + threadIdx.x;
    if (i < n4) *(float4*)&p[i * 4] = make_float4(0.f, 0.f, 0.f, 0.f);
}

// ---- fused GRU recurrent step. grid=(64, ndir), 128 thr. 8 hidden cols/CTA ----
__global__ void __launch_bounds__(128) gru_step(
    const float* __restrict__ hin_f, float* __restrict__ hout_f,
    const float* __restrict__ hin_b, float* __restrict__ hout_b,
    const float* __restrict__ GI_f, const float* __restrict__ GI_b,
    const float* __restrict__ Whh_f, const float* __restrict__ bhh_f,
    const float* __restrict__ Whh_b, const float* __restrict__ bhh_b,
    float* __restrict__ out_f, float* __restrict__ out_b,
    int t, int accum)
{
    int dir = blockIdx.y;
    const float* hin = dir ? hin_b : hin_f;
    float* hout      = dir ? hout_b : hout_f;
    const float* GI  = dir ? GI_b : GI_f;
    const float* Whh = dir ? Whh_b : Whh_f;
    const float* bhh = dir ? bhh_b : bhh_f;
    float* outp      = dir ? out_b : out_f;
    int tt = dir ? (Ss - 1 - t) : t;
    outp += (size_t)tt * Bb * Hh;

    int j0 = blockIdx.x * 8;
    int tid = threadIdx.x;
    int bq = (tid & 15) * 2;
    int jj = tid >> 4;
    int j = j0 + jj;

    __shared__ float ht[32][34];
    __shared__ float wsm[32][26];

    unsigned long long aR = 0, aZ = 0, aN = 0;

    for (int k0 = 0; k0 < Hh; k0 += 32) {
        {
            int b = tid >> 2;
            int kq = (tid & 3) * 8;
            const float* src = &hin[(size_t)b * Hh + k0 + kq];
            float4 v0 = *(const float4*)src;
            float4 v1 = *(const float4*)(src + 4);
            ht[kq + 0][b] = v0.x; ht[kq + 1][b] = v0.y;
            ht[kq + 2][b] = v0.z; ht[kq + 3][b] = v0.w;
            ht[kq + 4][b] = v1.x; ht[kq + 5][b] = v1.y;
            ht[kq + 6][b] = v1.z; ht[kq + 7][b] = v1.w;
        }
        for (int idx = tid; idx < 192; idx += 128) {
            int r = idx >> 3;
            int kq = (idx & 7) * 4;
            int g = r >> 3;
            int wr = g * Hh + j0 + (r & 7);
            float4 v = *(const float4*)&Whh[(size_t)wr * Hh + k0 + kq];
            wsm[kq + 0][r] = v.x; wsm[kq + 1][r] = v.y;
            wsm[kq + 2][r] = v.z; wsm[kq + 3][r] = v.w;
        }
        __syncthreads();
#pragma unroll
        for (int k = 0; k < 32; k++) {
            unsigned long long hv = *(const unsigned long long*)&ht[k][bq];
            ffma2(aR, dup2(wsm[k][jj]), hv);
            ffma2(aZ, dup2(wsm[k][8 + jj]), hv);
            ffma2(aN, dup2(wsm[k][16 + jj]), hv);
        }
        __syncthreads();
    }

    float2 gr = unpk(aR), gz = unpk(aZ), gn = unpk(aN);
    float grv[2] = {gr.x, gr.y}, gzv[2] = {gz.x, gz.y}, gnv[2] = {gn.x, gn.y};
    float br = bhh[j], bz = bhh[Hh + j], bn = bhh[2 * Hh + j];
#pragma unroll
    for (int q = 0; q < 2; q++) {
        int b = bq + q;
        const float* gi = &GI[((size_t)tt * Bb + b) * G3];
        float ir = gi[j], iz = gi[Hh + j], in_ = gi[2 * Hh + j];
        float hprev = hin[(size_t)b * Hh + j];
        float r = 1.f / (1.f + expf(-(ir + grv[q] + br)));
        float z = 1.f / (1.f + expf(-(iz + gzv[q] + bz)));
        float n = tanhf(in_ + r * (gnv[q] + bn));
        float hnew = (1.f - z) * n + z * hprev;
        hout[(size_t)b * Hh + j] = hnew;
        if (accum) outp[(size_t)b * Hh + j] += hnew;
        else       outp[(size_t)b * Hh + j] = hnew;
    }
}

// ---- batched attention: scores, softmax, context, concat [h2|ctx] ----
__global__ void __launch_bounds__(128) attn_kernel(
    const float* __restrict__ Hs, const float* __restrict__ enc_out,
    float* __restrict__ A2)
{
    int row = blockIdx.x;           // t*B + b
    int b = row & (Bb - 1);
    int tid = threadIdx.x;
    __shared__ float hsh[Hh];
    __shared__ float sc[Ss];

    for (int i = tid; i < Hh; i += 128) hsh[i] = Hs[(size_t)row * Hh + i];
    __syncthreads();

    int warp = tid >> 5, lane = tid & 31;
    for (int s = warp; s < Ss; s += 4) {
        const float* e = &enc_out[((size_t)s * Bb + b) * Hh];
        float p = 0.f;
        for (int k = lane; k < Hh; k += 32) p += hsh[k] * e[k];
#pragma unroll
        for (int o = 16; o > 0; o >>= 1) p += __shfl_xor_sync(0xffffffffu, p, o);
        if (lane == 0) sc[s] = p;
    }
    __syncthreads();

    if (tid < 32) {
        float v0 = sc[tid];
        float v1 = (tid + 32 < Ss) ? sc[tid + 32] : -1e30f;
        float m = fmaxf(v0, v1);
#pragma unroll
        for (int o = 16; o > 0; o >>= 1) m = fmaxf(m, __shfl_xor_sync(0xffffffffu, m, o));
        float e0 = expf(v0 - m);
        float e1 = (tid + 32 < Ss) ? expf(v1 - m) : 0.f;
        float ssum = e0 + e1;
#pragma unroll
        for (int o = 16; o > 0; o >>= 1) ssum += __shfl_xor_sync(0xffffffffu, ssum, o);
        float inv = 1.f / ssum;
        sc[tid] = e0 * inv;
        if (tid + 32 < Ss) sc[tid + 32] = e1 * inv;
    }
    __syncthreads();

    float c0 = 0, c1 = 0, c2 = 0, c3 = 0;
    for (int s = 0; s < Ss; s++) {
        float p = sc[s];
        const float* e = &enc_out[((size_t)s * Bb + b) * Hh];
        c0 += p * e[tid];       c1 += p * e[tid + 128];
        c2 += p * e[tid + 256]; c3 += p * e[tid + 384];
    }
    float* a2 = &A2[(size_t)row * (2 * Hh)];
    a2[tid] = hsh[tid];             a2[tid + 128] = hsh[tid + 128];
    a2[tid + 256] = hsh[tid + 256]; a2[tid + 384] = hsh[tid + 384];
    a2[Hh + tid] = c0;       a2[Hh + tid + 128] = c1;
    a2[Hh + tid + 256] = c2; a2[Hh + tid + 384] = c3;
}

// ---- launch ----
extern "C" void kernel_launch(void* const* d_in, const int* in_sizes, int n_in,
                              void* d_out, int out_size)
{
    const int*   toks    = (const int*)d_in[0];
    const int*   tgt     = (const int*)d_in[1];
    const float* enc_emb = (const float*)d_in[2];
    const float* Wih_f   = (const float*)d_in[3];
    const float* Whh_f   = (const float*)d_in[4];
    const float* bih_f   = (const float*)d_in[5];
    const float* bhh_f   = (const float*)d_in[6];
    const float* Wih_b   = (const float*)d_in[7];
    const float* Whh_b   = (const float*)d_in[8];
    const float* bih_b   = (const float*)d_in[9];
    const float* bhh_b   = (const float*)d_in[10];
    const float* dec_emb = (const float*)d_in[11];
    const float* dWih    = (const float*)d_in[12];
    const float* dWhh    = (const float*)d_in[13];
    const float* dbih    = (const float*)d_in[14];
    const float* dbhh    = (const float*)d_in[15];
    const float* Wc      = (const float*)d_in[16];
    const float* bc      = (const float*)d_in[17];
    const float* Wo      = (const float*)d_in[18];
    const float* bo      = (const float*)d_in[19];
    float* out = (float*)d_out;

    float* scr = nullptr;
    cudaGetSymbolAddress((void**)&scr, g_scratch);
    float* X   = scr + OFF_X;
    float* GIf = scr + OFF_GIF;
    float* GIb = scr + OFF_GIB;
    float* GId = scr + OFF_GID;
    float* Hsb = scr + OFF_HS;
    float* A2  = scr + OFF_A2;
    float* C1  = scr + OFF_C1;
    float* EO  = scr + OFF_ENCOUT;
    float* hf[2] = { scr + OFF_HENCF, scr + OFF_HENCF + Bb * Hh };
    float* hb[2] = { scr + OFF_HENCB, scr + OFF_HENCB + Bb * Hh };
    float* hd[2] = { scr + OFF_HD,    scr + OFF_HD    + Bb * Hh };

    // zero enc_out + h ping-pong buffers (contiguous 884736 floats)
    zero_kernel<<<432, 512>>>(EO, 884736 / 4);

    // ---- encoder ----
    embed_enc<<<Ss * Bb, 128>>>(toks, enc_emb, X);
    gemm_wt<<<dim3(12, 12), 256>>>(X, Wih_f, bih_f, GIf, 1536, 1536, 512, 0);
    gemm_wt<<<dim3(12, 12), 256>>>(X, Wih_b, bih_b, GIb, 1536, 1536, 512, 0);
    for (int t = 0; t < Ss; t++) {
        gru_step<<<dim3(64, 2), 128>>>(
            hf[t & 1], hf[(t + 1) & 1], hb[t & 1], hb[(t + 1) & 1],
            GIf, GIb, Whh_f, bhh_f, Whh_b, bhh_b, EO, EO, t, 1);
    }

    // dec_h0 = final fwd encoder state (lands in hf[0] after 48 steps)
    cudaMemcpyAsync(hd[0], hf[0], Bb * Hh * sizeof(float),
                    cudaMemcpyDeviceToDevice);

    // ---- decoder recurrence (teacher forcing: inputs known up front) ----
    embed_dec<<<Tt * Bb, 128>>>(tgt, dec_emb, X);
    gemm_wt<<<dim3(12, 12), 256>>>(X, dWih, dbih, GId, 1536, 1536, 512, 0);
    for (int t = 0; t < Tt; t++) {
        gru_step<<<dim3(64, 1), 128>>>(
            hd[t & 1], hd[(t + 1) & 1], hd[t & 1], hd[(t + 1) & 1],
            GId, GId, dWhh, dbhh, dWhh, dbhh, Hsb, Hsb, t, 0);
    }

    // ---- batched attention + output head ----
    attn_kernel<<<Tt * Bb, 128>>>(Hsb, EO, A2);
    gemm_wt<<<dim3(12, 4), 256>>>(A2, Wc, bc, C1, 1536, 512, 1024, 1);
    gemm_wt<<<dim3(12, 250), 256>>>(C1, Wo, bo, out, 1536, 32000, 512, 0);
}

// round 14
// speedup vs baseline: 1.0018x; 1.0018x over previous
#include <cuda_runtime.h>
#include <math.h>

#define Hh 512
#define Bb 32
#define Ss 48
#define Tt 48
#define G3 1536

// ---- scratch layout (floats) ----
#define OFF_X      0
#define OFF_GIF    786432
#define OFF_GIB    3145728
#define OFF_GID    5505024
#define OFF_HS     7864320
#define OFF_A2     8650752
#define OFF_C1     10223616
#define OFF_ENCOUT 11010048
#define OFF_HENCF  11796480
#define OFF_HENCB  11829248
#define OFF_HD     11862016
#define SCR_TOTAL  11894784

static __device__ float g_scratch[SCR_TOTAL];

// ---- packed f32x2 helpers (FFMA2) ----
__device__ __forceinline__ unsigned long long dup2(float x) {
    unsigned long long r;
    asm("mov.b64 %0, {%1, %1};" : "=l"(r) : "f"(x));
    return r;
}
__device__ __forceinline__ void ffma2(unsigned long long &c, unsigned long long a,
                                      unsigned long long b) {
    asm("fma.rn.f32x2 %0, %1, %2, %0;" : "+l"(c) : "l"(a), "l"(b));
}
__device__ __forceinline__ float2 unpk(unsigned long long v) {
    float2 r;
    asm("mov.b64 {%0, %1}, %2;" : "=f"(r.x), "=f"(r.y) : "l"(v));
    return r;
}

// ---- C[M,N] = A[M,K] @ W[N,K]^T + bias, optional tanh. 128x128x16 tiles ----
__global__ void __launch_bounds__(256) gemm_wt(
    const float* __restrict__ A, const float* __restrict__ W,
    const float* __restrict__ bias, float* __restrict__ C,
    int M, int N, int K, int act)
{
    __shared__ float As[16][132];
    __shared__ float Bs[16][132];
    const int m0 = blockIdx.x * 128;
    const int n0 = blockIdx.y * 128;
    const int tid = threadIdx.x;
    const int tx = tid & 15, ty = tid >> 4;
    const int lrow = tid >> 2;
    const int lk = (tid & 3) << 2;

    unsigned long long acc[8][4];
#pragma unroll
    for (int i = 0; i < 8; i++)
#pragma unroll
        for (int j = 0; j < 4; j++) acc[i][j] = 0ULL;

    for (int k0 = 0; k0 < K; k0 += 16) {
#pragma unroll
        for (int r = 0; r < 2; r++) {
            int row = lrow + r * 64;
            float4 va = *(const float4*)&A[(size_t)(m0 + row) * K + k0 + lk];
            As[lk + 0][row] = va.x; As[lk + 1][row] = va.y;
            As[lk + 2][row] = va.z; As[lk + 3][row] = va.w;
            float4 vw = *(const float4*)&W[(size_t)(n0 + row) * K + k0 + lk];
            Bs[lk + 0][row] = vw.x; Bs[lk + 1][row] = vw.y;
            Bs[lk + 2][row] = vw.z; Bs[lk + 3][row] = vw.w;
        }
        __syncthreads();
#pragma unroll
        for (int k = 0; k < 16; k++) {
            float4 a0 = *(const float4*)&As[k][ty * 8];
            float4 a1 = *(const float4*)&As[k][ty * 8 + 4];
            unsigned long long b0 = *(const unsigned long long*)&Bs[k][tx * 8];
            unsigned long long b1 = *(const unsigned long long*)&Bs[k][tx * 8 + 2];
            unsigned long long b2 = *(const unsigned long long*)&Bs[k][tx * 8 + 4];
            unsigned long long b3 = *(const unsigned long long*)&Bs[k][tx * 8 + 6];
            float av[8] = {a0.x, a0.y, a0.z, a0.w, a1.x, a1.y, a1.z, a1.w};
#pragma unroll
            for (int i = 0; i < 8; i++) {
                unsigned long long a2 = dup2(av[i]);
                ffma2(acc[i][0], a2, b0);
                ffma2(acc[i][1], a2, b1);
                ffma2(acc[i][2], a2, b2);
                ffma2(acc[i][3], a2, b3);
            }
        }
        __syncthreads();
    }
#pragma unroll
    for (int i = 0; i < 8; i++) {
        int m = m0 + ty * 8 + i;
#pragma unroll
        for (int j = 0; j < 4; j++) {
            int n = n0 + tx * 8 + j * 2;
            float2 v = unpk(acc[i][j]);
            v.x += bias[n]; v.y += bias[n + 1];
            if (act) { v.x = tanhf(v.x); v.y = tanhf(v.y); }
            *(float2*)&C[(size_t)m * N + n] = v;
        }
    }
}

// ---- embedding gathers ----
__global__ void embed_enc(const int* __restrict__ toks, const float* __restrict__ emb,
                          float* __restrict__ X)
{
    int row = blockIdx.x;
    int tok = toks[row];
    const float4* s = (const float4*)(emb + (size_t)tok * Hh);
    float4* d = (float4*)(X + (size_t)row * Hh);
    d[threadIdx.x] = s[threadIdx.x];
}
__global__ void embed_dec(const int* __restrict__ tgt, const float* __restrict__ emb,
                          float* __restrict__ X)
{
    int row = blockIdx.x;
    int tok = (row < Bb) ? 1 : tgt[row - Bb];   // SOS=1, then target[t-1]
    const float4* s = (const float4*)(emb + (size_t)tok * Hh);
    float4* d = (float4*)(X + (size_t)row * Hh);
    d[threadIdx.x] = s[threadIdx.x];
}

__global__ void zero_kernel(float* __restrict__ p, int n4)
{
    int i = blockIdx.x * blockDim.x + threadIdx.x;
    if (i < n4) *(float4*)&p[i * 4] = make_float4(0.f, 0.f, 0.f, 0.f);
}

// ---- fused GRU recurrent step. grid=(64, ndir), 128 thr. 8 hidden cols/CTA ----
__global__ void __launch_bounds__(128) gru_step(
    const float* __restrict__ hin_f, float* __restrict__ hout_f,
    const float* __restrict__ hin_b, float* __restrict__ hout_b,
    const float* __restrict__ GI_f, const float* __restrict__ GI_b,
    const float* __restrict__ Whh_f, const float* __restrict__ bhh_f,
    const float* __restrict__ Whh_b, const float* __restrict__ bhh_b,
    float* __restrict__ out_f, float* __restrict__ out_b,
    int t, int accum)
{
    int dir = blockIdx.y;
    const float* hin = dir ? hin_b : hin_f;
    float* hout      = dir ? hout_b : hout_f;
    const float* GI  = dir ? GI_b : GI_f;
    const float* Whh = dir ? Whh_b : Whh_f;
    const float* bhh = dir ? bhh_b : bhh_f;
    float* outp      = dir ? out_b : out_f;
    int tt = dir ? (Ss - 1 - t) : t;
    outp += (size_t)tt * Bb * Hh;

    int j0 = blockIdx.x * 8;
    int tid = threadIdx.x;
    int bq = (tid & 15) * 2;
    int jj = tid >> 4;
    int j = j0 + jj;

    __shared__ float ht[32][34];
    __shared__ float wsm[32][26];

    unsigned long long aR = 0, aZ = 0, aN = 0;

    for (int k0 = 0; k0 < Hh; k0 += 32) {
        {
            int b = tid >> 2;
            int kq = (tid & 3) * 8;
            const float* src = &hin[(size_t)b * Hh + k0 + kq];
            float4 v0 = *(const float4*)src;
            float4 v1 = *(const float4*)(src + 4);
            ht[kq + 0][b] = v0.x; ht[kq + 1][b] = v0.y;
            ht[kq + 2][b] = v0.z; ht[kq + 3][b] = v0.w;
            ht[kq + 4][b] = v1.x; ht[kq + 5][b] = v1.y;
            ht[kq + 6][b] = v1.z; ht[kq + 7][b] = v1.w;
        }
        for (int idx = tid; idx < 192; idx += 128) {
            int r = idx >> 3;
            int kq = (idx & 7) * 4;
            int g = r >> 3;
            int wr = g * Hh + j0 + (r & 7);
            float4 v = *(const float4*)&Whh[(size_t)wr * Hh + k0 + kq];
            wsm[kq + 0][r] = v.x; wsm[kq + 1][r] = v.y;
            wsm[kq + 2][r] = v.z; wsm[kq + 3][r] = v.w;
        }
        __syncthreads();
#pragma unroll
        for (int k = 0; k < 32; k++) {
            unsigned long long hv = *(const unsigned long long*)&ht[k][bq];
            ffma2(aR, dup2(wsm[k][jj]), hv);
            ffma2(aZ, dup2(wsm[k][8 + jj]), hv);
            ffma2(aN, dup2(wsm[k][16 + jj]), hv);
        }
        __syncthreads();
    }

    float2 gr = unpk(aR), gz = unpk(aZ), gn = unpk(aN);
    float grv[2] = {gr.x, gr.y}, gzv[2] = {gz.x, gz.y}, gnv[2] = {gn.x, gn.y};
    float br = bhh[j], bz = bhh[Hh + j], bn = bhh[2 * Hh + j];
#pragma unroll
    for (int q = 0; q < 2; q++) {
        int b = bq + q;
        const float* gi = &GI[((size_t)tt * Bb + b) * G3];
        float ir = gi[j], iz = gi[Hh + j], in_ = gi[2 * Hh + j];
        float hprev = hin[(size_t)b * Hh + j];
        float r = 1.f / (1.f + expf(-(ir + grv[q] + br)));
        float z = 1.f / (1.f + expf(-(iz + gzv[q] + bz)));
        float n = tanhf(in_ + r * (gnv[q] + bn));
        float hnew = (1.f - z) * n + z * hprev;
        hout[(size_t)b * Hh + j] = hnew;
        if (accum) outp[(size_t)b * Hh + j] += hnew;
        else       outp[(size_t)b * Hh + j] = hnew;
    }
}

// ---- batched attention: scores, softmax, context, concat [h2|ctx] ----
__global__ void __launch_bounds__(128) attn_kernel(
    const float* __restrict__ Hs, const float* __restrict__ enc_out,
    float* __restrict__ A2)
{
    int row = blockIdx.x;           // t*B + b
    int b = row & (Bb - 1);
    int tid = threadIdx.x;
    __shared__ float hsh[Hh];
    __shared__ float sc[Ss];

    for (int i = tid; i < Hh; i += 128) hsh[i] = Hs[(size_t)row * Hh + i];
    __syncthreads();

    int warp = tid >> 5, lane = tid & 31;
    for (int s = warp; s < Ss; s += 4) {
        const float* e = &enc_out[((size_t)s * Bb + b) * Hh];
        float p = 0.f;
        for (int k = lane; k < Hh; k += 32) p += hsh[k] * e[k];
#pragma unroll
        for (int o = 16; o > 0; o >>= 1) p += __shfl_xor_sync(0xffffffffu, p, o);
        if (lane == 0) sc[s] = p;
    }
    __syncthreads();

    if (tid < 32) {
        float v0 = sc[tid];
        float v1 = (tid + 32 < Ss) ? sc[tid + 32] : -1e30f;
        float m = fmaxf(v0, v1);
#pragma unroll
        for (int o = 16; o > 0; o >>= 1) m = fmaxf(m, __shfl_xor_sync(0xffffffffu, m, o));
        float e0 = expf(v0 - m);
        float e1 = (tid + 32 < Ss) ? expf(v1 - m) : 0.f;
        float ssum = e0 + e1;
#pragma unroll
        for (int o = 16; o > 0; o >>= 1) ssum += __shfl_xor_sync(0xffffffffu, ssum, o);
        float inv = 1.f / ssum;
        sc[tid] = e0 * inv;
        if (tid + 32 < Ss) sc[tid + 32] = e1 * inv;
    }
    __syncthreads();

    float c0 = 0, c1 = 0, c2 = 0, c3 = 0;
    for (int s = 0; s < Ss; s++) {
        float p = sc[s];
        const float* e = &enc_out[((size_t)s * Bb + b) * Hh];
        c0 += p * e[tid];       c1 += p * e[tid + 128];
        c2 += p * e[tid + 256]; c3 += p * e[tid + 384];
    }
    float* a2 = &A2[(size_t)row * (2 * Hh)];
    a2[tid] = hsh[tid];             a2[tid + 128] = hsh[tid + 128];
    a2[tid + 256] = hsh[tid + 256]; a2[tid + 384] = hsh[tid + 384];
    a2[Hh + tid] = c0;       a2[Hh + tid + 128] = c1;
    a2[Hh + tid + 256] = c2; a2[Hh + tid + 384] = c3;
}

// ---- launch ----
extern "C" void kernel_launch(void* const* d_in, const int* in_sizes, int n_in,
                              void* d_out, int out_size)
{
    const int*   toks    = (const int*)d_in[0];
    const int*   tgt     = (const int*)d_in[1];
    const float* enc_emb = (const float*)d_in[2];
    const float* Wih_f   = (const float*)d_in[3];
    const float* Whh_f   = (const float*)d_in[4];
    const float* bih_f   = (const float*)d_in[5];
    const float* bhh_f   = (const float*)d_in[6];
    const float* Wih_b   = (const float*)d_in[7];
    const float* Whh_b   = (const float*)d_in[8];
    const float* bih_b   = (const float*)d_in[9];
    const float* bhh_b   = (const float*)d_in[10];
    const float* dec_emb = (const float*)d_in[11];
    const float* dWih    = (const float*)d_in[12];
    const float* dWhh    = (const float*)d_in[13];
    const float* dbih    = (const float*)d_in[14];
    const float* dbhh    = (const float*)d_in[15];
    const float* Wc      = (const float*)d_in[16];
    const float* bc      = (const float*)d_in[17];
    const float* Wo      = (const float*)d_in[18];
    const float* bo      = (const float*)d_in[19];
    float* out = (float*)d_out;

    float* scr = nullptr;
    cudaGetSymbolAddress((void**)&scr, g_scratch);
    float* X   = scr + OFF_X;
    float* GIf = scr + OFF_GIF;
    float* GIb = scr + OFF_GIB;
    float* GId = scr + OFF_GID;
    float* Hsb = scr + OFF_HS;
    float* A2  = scr + OFF_A2;
    float* C1  = scr + OFF_C1;
    float* EO  = scr + OFF_ENCOUT;
    float* hf[2] = { scr + OFF_HENCF, scr + OFF_HENCF + Bb * Hh };
    float* hb[2] = { scr + OFF_HENCB, scr + OFF_HENCB + Bb * Hh };
    float* hd[2] = { scr + OFF_HD,    scr + OFF_HD    + Bb * Hh };

    // zero enc_out + h ping-pong buffers (contiguous 884736 floats)
    zero_kernel<<<432, 512>>>(EO, 884736 / 4);

    // ---- encoder ----
    embed_enc<<<Ss * Bb, 128>>>(toks, enc_emb, X);
    gemm_wt<<<dim3(12, 12), 256>>>(X, Wih_f, bih_f, GIf, 1536, 1536, 512, 0);
    gemm_wt<<<dim3(12, 12), 256>>>(X, Wih_b, bih_b, GIb, 1536, 1536, 512, 0);
    for (int t = 0; t < Ss; t++) {
        gru_step<<<dim3(64, 2), 128>>>(
            hf[t & 1], hf[(t + 1) & 1], hb[t & 1], hb[(t + 1) & 1],
            GIf, GIb, Whh_f, bhh_f, Whh_b, bhh_b, EO, EO, t, 1);
    }

    // dec_h0 = final fwd encoder state (lands in hf[0] after 48 steps)
    cudaMemcpyAsync(hd[0], hf[0], Bb * Hh * sizeof(float),
                    cudaMemcpyDeviceToDevice);

    // ---- decoder recurrence (teacher forcing: inputs known up front) ----
    embed_dec<<<Tt * Bb, 128>>>(tgt, dec_emb, X);
    gemm_wt<<<dim3(12, 12), 256>>>(X, dWih, dbih, GId, 1536, 1536, 512, 0);
    for (int t = 0; t < Tt; t++) {
        gru_step<<<dim3(64, 1), 128>>>(
            hd[t & 1], hd[(t + 1) & 1], hd[t & 1], hd[(t + 1) & 1],
            GId, GId, dWhh, dbhh, dWhh, dbhh, Hsb, Hsb, t, 0);
    }

    // ---- batched attention + output head ----
    attn_kernel<<<Tt * Bb, 128>>>(Hsb, EO, A2);
    gemm_wt<<<dim3(12, 4), 256>>>(A2, Wc, bc, C1, 1536, 512, 1024, 1);
    gemm_wt<<<dim3(12, 250), 256>>>(C1, Wo, bo, out, 1536, 32000, 512, 0);
}